// round 16
// baseline (speedup 1.0000x reference)
#include <cuda_runtime.h>
#include <cuda_bf16.h>
#include <math.h>

#define MTOK 262144   // B*H*W = 4*256*256
#define CDIM 128
#define HID  512

// ---------------- scratch (device globals: allocation-free) ----------------
__device__ __nv_bfloat16 g_xw[(size_t)MTOK*CDIM];  // LN1 + shift + window partition
__device__ __nv_bfloat16 g_ao[(size_t)MTOK*CDIM];  // attention output (window order)
__device__ __nv_bfloat16 g_wt[49152];              // Wqkv [384][128] bf16
__device__ __nv_bfloat16 g_tb[147456];             // tail blob: 18 slabs [128][64]

__device__ __forceinline__ int region(int a) { return a < 248 ? 0 : (a < 252 ? 1 : 2); }

__device__ __forceinline__ void mma_bf16(float c[4], const unsigned a[4], const unsigned b[2]) {
    asm volatile("mma.sync.aligned.m16n8k16.row.col.f32.bf16.bf16.f32 "
        "{%0,%1,%2,%3}, {%4,%5,%6,%7}, {%8,%9}, {%0,%1,%2,%3};\n"
        : "+f"(c[0]), "+f"(c[1]), "+f"(c[2]), "+f"(c[3])
        : "r"(a[0]), "r"(a[1]), "r"(a[2]), "r"(a[3]), "r"(b[0]), "r"(b[1]));
}
__device__ __forceinline__ void ldsm4(unsigned r[4], unsigned addr) {
    asm volatile("ldmatrix.sync.aligned.m8n8.x4.shared.b16 {%0,%1,%2,%3}, [%4];"
        : "=r"(r[0]), "=r"(r[1]), "=r"(r[2]), "=r"(r[3]) : "r"(addr));
}
__device__ __forceinline__ void ldsm2(unsigned r[2], unsigned addr) {
    asm volatile("ldmatrix.sync.aligned.m8n8.x2.shared.b16 {%0,%1}, [%2];"
        : "=r"(r[0]), "=r"(r[1]) : "r"(addr));
}
__device__ __forceinline__ void cp16(unsigned dst, const void* src) {
    asm volatile("cp.async.cg.shared.global [%0], [%1], 16;\n" :: "r"(dst), "l"(src));
}
#define CP_COMMIT asm volatile("cp.async.commit_group;\n" ::: "memory")
#define CP_WAIT1  asm volatile("cp.async.wait_group 1;\n" ::: "memory")
#define CP_WAIT0  asm volatile("cp.async.wait_group 0;\n" ::: "memory")

// window-order index m -> original token index (window reverse + roll(+4,+4))
__device__ __forceinline__ int perm_m(int m) {
    int b = m >> 16, w = (m >> 6) & 1023, t = m & 63;
    int wh = w >> 5, ww = w & 31, ti = t >> 3, tj = t & 7;
    int r = (wh*8 + ti + 4) & 255;
    int c = (ww*8 + tj + 4) & 255;
    return (b << 16) | (r << 8) | c;
}
__device__ __forceinline__ unsigned packbf(float a, float b) {
    __nv_bfloat162 t = __floats2bfloat162_rn(a, b);
    return *(unsigned*)&t;
}
__device__ __forceinline__ unsigned short bf16u(float a) {
    __nv_bfloat16 t = __float2bfloat16(a);
    return *(unsigned short*)&t;
}
__device__ __forceinline__ float gelu_f(float v) {
    return 0.5f*v*(1.0f + erff(v*0.70710678118654752f));
}

// ---------------- fused weight prep ----------------------------------------
__global__ void prep_all(const float* __restrict__ qw, const float* __restrict__ kw,
                         const float* __restrict__ vw, const float* __restrict__ pw,
                         const float* __restrict__ f1w, const float* __restrict__ f2w,
                         __nv_bfloat16* __restrict__ wt, __nv_bfloat16* __restrict__ tb)
{
    int idx = blockIdx.x * 256 + threadIdx.x;     // 0..196607
    if (idx < 49152) {
        int seg = idx >> 14;                      // 0=q,1=k,2=v
        int rel = idx & 16383;
        int n = rel >> 7, k = rel & 127;
        const float* src = seg == 0 ? qw : (seg == 1 ? kw : vw);
        wt[idx] = __float2bfloat16(src[k*128 + n]);
    } else {
        int i2 = idx - 49152;                     // 0..147455
        int st = i2 >> 13;                        // slab 0..17
        int rel = i2 & 8191;
        int r = rel >> 6, c = rel & 63;
        float v;
        if (st < 2) {
            v = pw[(st*64 + c)*128 + r];
        } else {
            int t = st - 2, ch = t >> 2, s = t & 3;
            if (s < 2) v = f1w[(s*64 + c)*512 + ch*128 + r];
            else       v = f2w[(ch*128 + (s-2)*64 + c)*128 + r];
        }
        tb[i2] = __float2bfloat16(v);
    }
}

// ---------------- LayerNorm (fused with shift+window gather), bf16 out -----
__global__ void ln_kernel(const float* __restrict__ in, const float* __restrict__ gamma,
                          const float* __restrict__ beta, __nv_bfloat16* __restrict__ out)
{
    int token = blockIdx.x * 8 + (threadIdx.x >> 5);
    int lane  = threadIdx.x & 31;
    int src = perm_m(token);
    float4 xv = ((const float4*)in)[(size_t)src*32 + lane];
    float s  = xv.x + xv.y + xv.z + xv.w;
    float sq = xv.x*xv.x + xv.y*xv.y + xv.z*xv.z + xv.w*xv.w;
    #pragma unroll
    for (int o = 16; o; o >>= 1) {
        s  += __shfl_xor_sync(0xffffffffu, s,  o);
        sq += __shfl_xor_sync(0xffffffffu, sq, o);
    }
    float mean = s * (1.f/128.f);
    float var  = sq * (1.f/128.f) - mean*mean;
    float rstd = rsqrtf(var + 1e-5f);
    float4 g  = ((const float4*)gamma)[lane];
    float4 bt = ((const float4*)beta)[lane];
    uint2 pk;
    pk.x = packbf((xv.x - mean)*rstd*g.x + bt.x, (xv.y - mean)*rstd*g.y + bt.y);
    pk.y = packbf((xv.z - mean)*rstd*g.z + bt.z, (xv.w - mean)*rstd*g.w + bt.w);
    ((uint2*)out)[(size_t)token*32 + lane] = pk;
}

// ---------------- fused QKV + windowed attention (unchanged from R15) ------
#define AQ_XW   0
#define AQ_WB   4352
#define AQ_PS   0
#define AQ_QS   9472
#define AQ_KS   13824
#define AQ_VT   18176
#define AQ_RPB  22784
#define AQ_LAB  23684
#define AQ_RM   23748
#define AQ_RS   24260
#define AQ_SMEM (24772*4)

__global__ void __launch_bounds__(256, 2) qkv_attn(
    const __nv_bfloat16* __restrict__ xw,
    const __nv_bfloat16* __restrict__ wqkv,   // [384][128]
    const float* __restrict__ qb, const float* __restrict__ kb, const float* __restrict__ vb,
    const float* __restrict__ rpb, float scale,
    __nv_bfloat16* __restrict__ out)
{
    extern __shared__ unsigned sm[];
    unsigned* Xw = sm + AQ_XW;
    unsigned* Qs = sm + AQ_QS;
    unsigned* Ks = sm + AQ_KS;
    float*    rpb_s = (float*)(sm + AQ_RPB);
    int*      lab_s = (int*)(sm + AQ_LAB);
    float*    redm  = (float*)(sm + AQ_RM);
    float*    redsm = (float*)(sm + AQ_RS);
    unsigned short* vtb = (unsigned short*)(sm + AQ_VT);

    const int win  = blockIdx.x;
    const int tid  = threadIdx.x;
    const int lane = tid & 31;
    const int lr   = lane >> 2;
    const int lc   = lane & 3;
    const int wid  = tid >> 5;
    const int wloc = win & 1023;
    const int wh = wloc >> 5, ww = wloc & 31;

    const int a_lm   = (lane & 7) + ((lane >> 3) & 1)*8;
    const int a_kadd = (lane >> 4) << 2;
    const int b_lm   = lane & 7;
    const int b_kadd = ((lane >> 3) & 1) << 2;

    const unsigned sm_u  = (unsigned)__cvta_generic_to_shared(sm);
    const unsigned xw_u  = sm_u + AQ_XW*4;
    const unsigned wb_u  = sm_u + AQ_WB*4;
    const unsigned qs_u  = sm_u + AQ_QS*4;
    const unsigned ks_u  = sm_u + AQ_KS*4;
    const unsigned WBB = 128*20*4;

    #define WISSUE(st_, buf_) { \
        int c_ = (st_) >> 2, ko_ = ((st_) & 3)*32; \
        _Pragma("unroll") \
        for (int s_ = 0; s_ < 2; s_++) { \
            int slot_ = tid + 256*s_; \
            int rw_ = slot_ >> 2, cc_ = slot_ & 3; \
            cp16(wb_u + (buf_)*WBB + (rw_*20 + cc_*4)*4, \
                 wqkv + (size_t)(c_*128 + rw_)*128 + ko_ + cc_*8); \
        } CP_COMMIT; }

    {
        const __nv_bfloat16* xp = xw + (size_t)win*64*128;
        #pragma unroll
        for (int s_ = 0; s_ < 4; s_++) {
            int slot = tid + 256*s_;
            int row = slot >> 4, c4 = slot & 15;
            cp16(xw_u + (row*68 + c4*4)*4, xp + (size_t)row*128 + c4*8);
        }
        WISSUE(0, 0);
    }
    WISSUE(1, 1);

    for (int idx = tid; idx < 900; idx += 256) rpb_s[idx] = rpb[idx];
    if (tid < 64) lab_s[tid] = 3*region(wh*8 + (tid >> 3)) + region(ww*8 + (tid & 7));

    const int wm = wid >> 2;
    const int wn = wid & 3;
    const int a_row = wm*32 + lr;
    float acc[2][4][4];

    CP_WAIT1;
    __syncthreads();

    for (int st = 0; st < 12; st++) {
        if (st + 1 < 12) { WISSUE(st + 1, (st + 1) & 1); CP_WAIT1; }
        else             { CP_WAIT0; }
        if (st > 0) __syncthreads();

        if ((st & 3) == 0) {
            #pragma unroll
            for (int i = 0; i < 2; i++)
                #pragma unroll
                for (int j = 0; j < 4; j++)
                    #pragma unroll
                    for (int c = 0; c < 4; c++) acc[i][j][c] = 0.f;
        }
        {
            const unsigned bslu = wb_u + (st & 1)*WBB;
            const int koff = (st & 3)*16;
            #pragma unroll
            for (int kk2 = 0; kk2 < 16; kk2 += 8) {
                unsigned afr[2][4];
                ldsm4(afr[0], xw_u + ((wm*32 + a_lm)*68      + koff + kk2 + a_kadd)*4);
                ldsm4(afr[1], xw_u + ((wm*32 + 16 + a_lm)*68 + koff + kk2 + a_kadd)*4);
                #pragma unroll
                for (int j = 0; j < 4; j++) {
                    unsigned bfr[2];
                    ldsm2(bfr, bslu + ((wn*32 + j*8 + b_lm)*20 + kk2 + b_kadd)*4);
                    #pragma unroll
                    for (int i = 0; i < 2; i++)
                        mma_bf16(acc[i][j], afr[i], bfr);
                }
            }
        }
        if ((st & 3) == 3) {
            int chunk = st >> 2;   // 0=Q, 1=K, 2=V
            #pragma unroll
            for (int i = 0; i < 2; i++) {
                #pragma unroll
                for (int half = 0; half < 2; half++) {
                    int row = a_row + i*16 + half*8;
                    #pragma unroll
                    for (int j = 0; j < 4; j++) {
                        int n = wn*32 + j*8 + 2*lc;
                        if (chunk == 0) {
                            float v0 = (acc[i][j][half*2 + 0] + qb[n]) * scale;
                            float v1 = (acc[i][j][half*2 + 1] + qb[n+1]) * scale;
                            Qs[row*68 + wn*16 + j*4 + lc] = packbf(v0, v1);
                        } else if (chunk == 1) {
                            float v0 = acc[i][j][half*2 + 0] + kb[n];
                            float v1 = acc[i][j][half*2 + 1] + kb[n+1];
                            Ks[row*68 + wn*16 + j*4 + lc] = packbf(v0, v1);
                        } else {
                            float v0 = acc[i][j][half*2 + 0] + vb[n];
                            float v1 = acc[i][j][half*2 + 1] + vb[n+1];
                            int h0 = n >> 5,  nl0 = n & 31;
                            int h1 = (n+1) >> 5, nl1 = (n+1) & 31;
                            vtb[h0*2304 + nl0*72 + row] = bf16u(v0);
                            vtb[h1*2304 + nl1*72 + row] = bf16u(v1);
                        }
                    }
                }
            }
        }
        __syncthreads();
    }
    #undef WISSUE

    const int head = wid >> 1;
    const int w    = wid & 1;
    const unsigned ps_u = sm_u + AQ_PS*4 + head*2304*4;
    const unsigned vt_u = sm_u + AQ_VT*4 + head*1152*4;
    unsigned* Ps   = sm + AQ_PS + head*2304;
    float* redm_h  = redm  + head*128;
    float* reds_h  = redsm + head*128;
    const int hq   = head*16;

    float s[4][4][4];
    #pragma unroll
    for (int i = 0; i < 4; i++)
        #pragma unroll
        for (int j = 0; j < 4; j++)
            #pragma unroll
            for (int c = 0; c < 4; c++) s[i][j][c] = 0.f;

    const int nb0 = w*32;
    #pragma unroll
    for (int kk2 = 0; kk2 < 16; kk2 += 8) {
        unsigned afr[4][4], bfr[4][2];
        #pragma unroll
        for (int i = 0; i < 4; i++)
            ldsm4(afr[i], qs_u + ((i*16 + a_lm)*68 + hq + kk2 + a_kadd)*4);
        #pragma unroll
        for (int j = 0; j < 4; j++)
            ldsm2(bfr[j], ks_u + ((nb0 + j*8 + b_lm)*68 + hq + kk2 + b_kadd)*4);
        #pragma unroll
        for (int i = 0; i < 4; i++)
            #pragma unroll
            for (int j = 0; j < 4; j++)
                mma_bf16(s[i][j], afr[i], bfr[j]);
    }

    #pragma unroll
    for (int i = 0; i < 4; i++) {
        #pragma unroll
        for (int half = 0; half < 2; half++) {
            int r = i*16 + lr + half*8;
            int labr = lab_s[r];
            int ti = r >> 3, tj = r & 7;
            float m_ = -1e30f;
            #pragma unroll
            for (int j = 0; j < 4; j++) {
                #pragma unroll
                for (int e = 0; e < 2; e++) {
                    int c = nb0 + j*8 + 2*lc + e;
                    int ki = c >> 3, kj = c & 7;
                    float val = s[i][j][half*2 + e]
                              + rpb_s[((ti - ki + 7)*15 + (tj - kj + 7))*4 + head];
                    if (lab_s[c] != labr) val -= 100.f;
                    s[i][j][half*2 + e] = val;
                    m_ = fmaxf(m_, val);
                }
            }
            m_ = fmaxf(m_, __shfl_xor_sync(0xffffffffu, m_, 1));
            m_ = fmaxf(m_, __shfl_xor_sync(0xffffffffu, m_, 2));
            if (lc == 0) redm_h[r*2 + w] = m_;
        }
    }
    __syncthreads();

    #pragma unroll
    for (int i = 0; i < 4; i++) {
        #pragma unroll
        for (int half = 0; half < 2; half++) {
            int r = i*16 + lr + half*8;
            float mx = fmaxf(redm_h[r*2], redm_h[r*2 + 1]);
            float sum = 0.f;
            #pragma unroll
            for (int j = 0; j < 4; j++) {
                float e0 = __expf(s[i][j][half*2 + 0] - mx);
                float e1 = __expf(s[i][j][half*2 + 1] - mx);
                sum += e0 + e1;
                Ps[r*36 + 16*w + j*4 + lc] = packbf(e0, e1);
            }
            sum += __shfl_xor_sync(0xffffffffu, sum, 1);
            sum += __shfl_xor_sync(0xffffffffu, sum, 2);
            if (lc == 0) reds_h[r*2 + w] = sum;
        }
    }
    __syncthreads();

    float o[2][4][4];
    #pragma unroll
    for (int i = 0; i < 2; i++)
        #pragma unroll
        for (int j = 0; j < 4; j++)
            #pragma unroll
            for (int c = 0; c < 4; c++) o[i][j][c] = 0.f;

    const int mb = w*32;
    #pragma unroll
    for (int kb = 0; kb < 4; kb++) {
        unsigned afr[2][4], bfr[4][2];
        #pragma unroll
        for (int i = 0; i < 2; i++)
            ldsm4(afr[i], ps_u + ((mb + i*16 + a_lm)*36 + kb*8 + a_kadd)*4);
        #pragma unroll
        for (int j = 0; j < 4; j++)
            ldsm2(bfr[j], vt_u + ((j*8 + b_lm)*36 + kb*8 + b_kadd)*4);
        #pragma unroll
        for (int i = 0; i < 2; i++)
            #pragma unroll
            for (int j = 0; j < 4; j++)
                mma_bf16(o[i][j], afr[i], bfr[j]);
    }

    #pragma unroll
    for (int i = 0; i < 2; i++) {
        #pragma unroll
        for (int half = 0; half < 2; half++) {
            int r = mb + i*16 + lr + half*8;
            float inv = 1.f / (reds_h[r*2] + reds_h[r*2 + 1]);
            size_t ob = (size_t)win*64*128 + (size_t)r*128 + head*32;
            #pragma unroll
            for (int j = 0; j < 4; j++) {
                int n = j*8 + 2*lc;
                float v0 = o[i][j][half*2 + 0] * inv;
                float v1 = o[i][j][half*2 + 1] * inv;
                *(unsigned*)&out[ob + n] = packbf(v0, v1);
            }
        }
    }
}

// ---------------- fused tail: M=128, 512 threads, 1 block/SM ---------------
// 16 warps = 4m x 4n, warp tile 32x32. 18 unrolled single-barrier stages.
// smem (uints): As 128*68 | L2s 128*68 | Hc 128*68 | Xs f32 128*132
//               | Bs 2*128*36 | red_s 512 | red_q 512
#define T_AS 0
#define T_L2 8704
#define T_HC 17408
#define T_XS 26112
#define T_BS 43008
#define T_RS 52224
#define T_RQ 52736
#define TAIL_SMEM (53248*4)

__global__ void __launch_bounds__(512, 1) tail_fused(
    const __nv_bfloat16* __restrict__ ao,
    const __nv_bfloat16* __restrict__ blob,
    const float* __restrict__ pb, const float* __restrict__ b1, const float* __restrict__ b2,
    const float* __restrict__ hs,
    const float* __restrict__ gamma, const float* __restrict__ beta,
    float* __restrict__ outp)
{
    extern __shared__ unsigned sm[];
    unsigned* L2s = sm + T_L2;
    unsigned* Hc  = sm + T_HC;
    float*    Xs  = (float*)(sm + T_XS);
    float*    red_s = (float*)(sm + T_RS);
    float*    red_q = (float*)(sm + T_RQ);

    const int tid  = threadIdx.x;
    const int lane = tid & 31;
    const int lr   = lane >> 2;
    const int lc   = lane & 3;
    const int wid  = tid >> 5;          // 0..15
    const int wm   = wid >> 2;          // 0..3
    const int wn   = wid & 3;           // 0..3
    const int m0   = blockIdx.x * 128;
    const int a_row = wm*32 + lr;

    const int a_lm   = (lane & 7) + ((lane >> 3) & 1)*8;
    const int a_kadd = (lane >> 4) << 2;
    const int b_lm   = lane & 7;
    const int b_kadd = ((lane >> 3) & 1) << 2;

    const unsigned sm_u = (unsigned)__cvta_generic_to_shared(sm);
    const unsigned as_u = sm_u + T_AS*4;
    const unsigned l2_u = sm_u + T_L2*4;
    const unsigned hc_u = sm_u + T_HC*4;
    const unsigned xs_u = sm_u + T_XS*4;
    const unsigned bs_u = sm_u + T_BS*4;
    const unsigned BSB = 128*36*4;

    const unsigned a_off0 = ((wm*32 + a_lm)*68      + a_kadd)*4;
    const unsigned a_off1 = ((wm*32 + 16 + a_lm)*68 + a_kadd)*4;
    const unsigned b_off  = ((wn*32 + b_lm)*36 + b_kadd)*4;

    #define ISSUE_ST(st_) { \
        const __nv_bfloat16* W_ = blob + (size_t)(st_)*8192; \
        const unsigned dst_ = bs_u + (((st_) & 1))*BSB; \
        _Pragma("unroll") \
        for (int s_ = 0; s_ < 2; s_++) { \
            int slot_ = tid + 512*s_; \
            int rw_ = slot_ >> 3, c_ = slot_ & 7; \
            cp16(dst_ + (rw_*36 + c_*4)*4, W_ + rw_*64 + c_*8); \
        } CP_COMMIT; }

    // prologue: ao tile (128x128) + hs[perm] rows + weight slab 0
    {
        const __nv_bfloat16* aop = ao + (size_t)m0 * 128;
        #pragma unroll
        for (int s_ = 0; s_ < 4; s_++) {
            int slot = tid + 512*s_;
            int row = slot >> 4, c4 = slot & 15;
            cp16(as_u + (row*68 + c4*4)*4, aop + (size_t)row*128 + c4*8);
        }
        #pragma unroll
        for (int s_ = 0; s_ < 8; s_++) {
            int slot = tid + 512*s_;
            int row = slot >> 5, q4 = slot & 31;
            cp16(xs_u + (row*132 + q4*4)*4,
                 hs + (size_t)perm_m(m0 + row)*128 + q4*4);
        }
        ISSUE_ST(0);
    }

    float acc1[2][4][4], acc2[2][4][4];
    #pragma unroll
    for (int i = 0; i < 2; i++)
        #pragma unroll
        for (int j = 0; j < 4; j++)
            #pragma unroll
            for (int c = 0; c < 4; c++) { acc1[i][j][c] = 0.f; acc2[i][j][c] = 0.f; }

    #define STAGE_MMA(SRCU, KOFF, ACC, STC) { \
        const unsigned bslu = bs_u + ((STC) & 1)*BSB; \
        _Pragma("unroll") \
        for (int kk2 = 0; kk2 < 32; kk2 += 8) { \
            unsigned afr[2][4]; \
            ldsm4(afr[0], (SRCU) + a_off0 + ((KOFF) + kk2)*4); \
            ldsm4(afr[1], (SRCU) + a_off1 + ((KOFF) + kk2)*4); \
            _Pragma("unroll") \
            for (int j = 0; j < 4; j++) { \
                unsigned bfr[2]; \
                ldsm2(bfr, bslu + b_off + (j*8*36 + kk2)*4); \
                _Pragma("unroll") \
                for (int i = 0; i < 2; i++) \
                    mma_bf16(ACC[i][j], afr[i], bfr); \
            } } }

    #define DO_STAGE(STC, HASNEXT, SRCU, KOFF, ACC) { \
        CP_WAIT0; \
        __syncthreads(); \
        if (HASNEXT) ISSUE_ST((STC) + 1); \
        STAGE_MMA(SRCU, KOFF, ACC, STC); }

    // ---- proj: stages 0,1 ----
    DO_STAGE(0, 1, as_u, 0,  acc1);
    DO_STAGE(1, 1, as_u, 32, acc1);

    // proj epilogue: x = acc + pb + hs; LN2 -> L2s
    {
        #pragma unroll
        for (int i = 0; i < 2; i++) {
            #pragma unroll
            for (int half = 0; half < 2; half++) {
                int row = a_row + i*16 + half*8;
                float s = 0.f, q = 0.f;
                #pragma unroll
                for (int j = 0; j < 4; j++) {
                    int n = wn*32 + j*8 + 2*lc;
                    float x0 = acc1[i][j][half*2 + 0] + pb[n]   + Xs[row*132 + n];
                    float x1 = acc1[i][j][half*2 + 1] + pb[n+1] + Xs[row*132 + n + 1];
                    *(float2*)&Xs[row*132 + n] = make_float2(x0, x1);
                    s += x0 + x1;
                    q += x0*x0 + x1*x1;
                }
                s += __shfl_xor_sync(0xffffffffu, s, 1);
                s += __shfl_xor_sync(0xffffffffu, s, 2);
                q += __shfl_xor_sync(0xffffffffu, q, 1);
                q += __shfl_xor_sync(0xffffffffu, q, 2);
                if (lc == 0) { red_s[row*4 + wn] = s; red_q[row*4 + wn] = q; }
            }
        }
        __syncthreads();
        #pragma unroll
        for (int i = 0; i < 2; i++) {
            #pragma unroll
            for (int half = 0; half < 2; half++) {
                int row = a_row + i*16 + half*8;
                float s = red_s[row*4+0] + red_s[row*4+1] + red_s[row*4+2] + red_s[row*4+3];
                float q = red_q[row*4+0] + red_q[row*4+1] + red_q[row*4+2] + red_q[row*4+3];
                float mu = s * (1.f/128.f);
                float var = q * (1.f/128.f) - mu*mu;
                float rstd = rsqrtf(var + 1e-5f);
                #pragma unroll
                for (int j = 0; j < 4; j++) {
                    int n = wn*32 + j*8 + 2*lc;
                    float x0 = Xs[row*132 + n];
                    float x1 = Xs[row*132 + n + 1];
                    float l0 = (x0 - mu)*rstd*gamma[n]   + beta[n];
                    float l1 = (x1 - mu)*rstd*gamma[n+1] + beta[n+1];
                    L2s[row*68 + wn*16 + j*4 + lc] = packbf(l0, l1);
                }
            }
        }
    }

    // ---- MLP: 4 chunks x (fc1 a,b + gelu + fc2 a,b), fully unrolled -------
    #pragma unroll
    for (int ch = 0; ch < 4; ch++) {
        const int st0 = 2 + ch*4;
        #pragma unroll
        for (int i = 0; i < 2; i++)
            #pragma unroll
            for (int j = 0; j < 4; j++)
                #pragma unroll
                for (int c = 0; c < 4; c++) acc1[i][j][c] = 0.f;

        DO_STAGE(st0 + 0, 1, l2_u, 0,  acc1);
        DO_STAGE(st0 + 1, 1, l2_u, 32, acc1);

        // gelu epilogue -> Hc
        #pragma unroll
        for (int i = 0; i < 2; i++) {
            #pragma unroll
            for (int half = 0; half < 2; half++) {
                int row = a_row + i*16 + half*8;
                #pragma unroll
                for (int j = 0; j < 4; j++) {
                    int n = wn*32 + j*8 + 2*lc;
                    float v0 = gelu_f(acc1[i][j][half*2 + 0] + b1[ch*128 + n]);
                    float v1 = gelu_f(acc1[i][j][half*2 + 1] + b1[ch*128 + n + 1]);
                    Hc[row*68 + wn*16 + j*4 + lc] = packbf(v0, v1);
                }
            }
        }

        DO_STAGE(st0 + 2, 1,               hc_u, 0,  acc2);
        DO_STAGE(st0 + 3, (st0 + 3) < 17,  hc_u, 32, acc2);
    }
    #undef DO_STAGE
    #undef STAGE_MMA
    #undef ISSUE_ST

    // final epilogue: out[perm(m)] = x + mlp_out + b2
    #pragma unroll
    for (int i = 0; i < 2; i++) {
        #pragma unroll
        for (int half = 0; half < 2; half++) {
            int rloc = a_row + i*16 + half*8;
            int m = m0 + rloc;
            size_t dstrow = (size_t)perm_m(m) * 128;
            #pragma unroll
            for (int j = 0; j < 4; j++) {
                int n = wn*32 + j*8 + 2*lc;
                float v0 = acc2[i][j][half*2 + 0] + b2[n]   + Xs[rloc*132 + n];
                float v1 = acc2[i][j][half*2 + 1] + b2[n+1] + Xs[rloc*132 + n + 1];
                *(float2*)&outp[dstrow + n] = make_float2(v0, v1);
            }
        }
    }
}

// ---------------------------------------------------------------------------
extern "C" void kernel_launch(void* const* d_in, const int* in_sizes, int n_in,
                              void* d_out, int out_size)
{
    const float* hs   = (const float*)d_in[0];
    const float* l1s  = (const float*)d_in[1];
    const float* l1b  = (const float*)d_in[2];
    const float* qw   = (const float*)d_in[3];
    const float* qb   = (const float*)d_in[4];
    const float* kw   = (const float*)d_in[5];
    const float* kb   = (const float*)d_in[6];
    const float* vw   = (const float*)d_in[7];
    const float* vb   = (const float*)d_in[8];
    const float* pw   = (const float*)d_in[9];
    const float* pb   = (const float*)d_in[10];
    const float* rpb  = (const float*)d_in[11];
    const float* l2s  = (const float*)d_in[12];
    const float* l2b  = (const float*)d_in[13];
    const float* f1w  = (const float*)d_in[14];
    const float* f1b  = (const float*)d_in[15];
    const float* f2w  = (const float*)d_in[16];
    const float* f2b  = (const float*)d_in[17];
    float* outp = (float*)d_out;

    __nv_bfloat16 *xw, *ao, *wt, *tb;
    cudaGetSymbolAddress((void**)&xw, g_xw);
    cudaGetSymbolAddress((void**)&ao, g_ao);
    cudaGetSymbolAddress((void**)&wt, g_wt);
    cudaGetSymbolAddress((void**)&tb, g_tb);

    cudaFuncSetAttribute(qkv_attn,   cudaFuncAttributeMaxDynamicSharedMemorySize, AQ_SMEM);
    cudaFuncSetAttribute(tail_fused, cudaFuncAttributeMaxDynamicSharedMemorySize, TAIL_SMEM);

    const float qscale = 0.17677669529663687f;  // 1/sqrt(32)

    // 0. fused weight prep (Wqkv + tail blob)
    prep_all<<<768, 256>>>(qw, kw, vw, pw, f1w, f2w, wt, tb);
    // 1. LN1 + shift + window partition (bf16 out)
    ln_kernel<<<MTOK/8, 256>>>(hs, l1s, l1b, xw);
    // 2. fused QKV + windowed attention (one block per window)
    qkv_attn<<<4096, 256, AQ_SMEM>>>(xw, wt, qb, kb, vb, rpb, qscale, ao);
    // 3. fused tail: proj + shortcut + LN2 + fc1 + GELU + fc2 + residual (M=128)
    tail_fused<<<MTOK/128, 512, TAIL_SMEM>>>(ao, tb, pb, f1b, f2b,
                                             hs, l2s, l2b, outp);
}

// round 17
// speedup vs baseline: 1.1112x; 1.1112x over previous
#include <cuda_runtime.h>
#include <cuda_bf16.h>
#include <math.h>

#define MTOK 262144   // B*H*W = 4*256*256
#define CDIM 128
#define HID  512

// ---------------- scratch (device globals: allocation-free) ----------------
__device__ __nv_bfloat16 g_xw[(size_t)MTOK*CDIM];  // LN1 + shift + window partition
__device__ __nv_bfloat16 g_ao[(size_t)MTOK*CDIM];  // attention output (window order)
__device__ __nv_bfloat16 g_wt[49152];              // Wqkv [384][128] bf16
__device__ __nv_bfloat16 g_tb[147456];             // tail blob: 18 slabs [128][64]

__device__ __forceinline__ int region(int a) { return a < 248 ? 0 : (a < 252 ? 1 : 2); }

__device__ __forceinline__ void mma_bf16(float c[4], const unsigned a[4], const unsigned b[2]) {
    asm volatile("mma.sync.aligned.m16n8k16.row.col.f32.bf16.bf16.f32 "
        "{%0,%1,%2,%3}, {%4,%5,%6,%7}, {%8,%9}, {%0,%1,%2,%3};\n"
        : "+f"(c[0]), "+f"(c[1]), "+f"(c[2]), "+f"(c[3])
        : "r"(a[0]), "r"(a[1]), "r"(a[2]), "r"(a[3]), "r"(b[0]), "r"(b[1]));
}
__device__ __forceinline__ void ldsm4(unsigned r[4], unsigned addr) {
    asm volatile("ldmatrix.sync.aligned.m8n8.x4.shared.b16 {%0,%1,%2,%3}, [%4];"
        : "=r"(r[0]), "=r"(r[1]), "=r"(r[2]), "=r"(r[3]) : "r"(addr));
}
__device__ __forceinline__ void ldsm2(unsigned r[2], unsigned addr) {
    asm volatile("ldmatrix.sync.aligned.m8n8.x2.shared.b16 {%0,%1}, [%2];"
        : "=r"(r[0]), "=r"(r[1]) : "r"(addr));
}
__device__ __forceinline__ void cp16(unsigned dst, const void* src) {
    asm volatile("cp.async.cg.shared.global [%0], [%1], 16;\n" :: "r"(dst), "l"(src));
}
#define CP_COMMIT asm volatile("cp.async.commit_group;\n" ::: "memory")
#define CP_WAIT0  asm volatile("cp.async.wait_group 0;\n" ::: "memory")

// window-order index m -> original token index (window reverse + roll(+4,+4))
__device__ __forceinline__ int perm_m(int m) {
    int b = m >> 16, w = (m >> 6) & 1023, t = m & 63;
    int wh = w >> 5, ww = w & 31, ti = t >> 3, tj = t & 7;
    int r = (wh*8 + ti + 4) & 255;
    int c = (ww*8 + tj + 4) & 255;
    return (b << 16) | (r << 8) | c;
}
__device__ __forceinline__ unsigned packbf(float a, float b) {
    __nv_bfloat162 t = __floats2bfloat162_rn(a, b);
    return *(unsigned*)&t;
}
__device__ __forceinline__ unsigned short bf16u(float a) {
    __nv_bfloat16 t = __float2bfloat16(a);
    return *(unsigned short*)&t;
}
__device__ __forceinline__ float gelu_f(float v) {
    return 0.5f*v*(1.0f + erff(v*0.70710678118654752f));
}

// ---------------- fused weight prep ----------------------------------------
__global__ void prep_all(const float* __restrict__ qw, const float* __restrict__ kw,
                         const float* __restrict__ vw, const float* __restrict__ pw,
                         const float* __restrict__ f1w, const float* __restrict__ f2w,
                         __nv_bfloat16* __restrict__ wt, __nv_bfloat16* __restrict__ tb)
{
    int idx = blockIdx.x * 256 + threadIdx.x;     // 0..196607
    if (idx < 49152) {
        int seg = idx >> 14;                      // 0=q,1=k,2=v
        int rel = idx & 16383;
        int n = rel >> 7, k = rel & 127;
        const float* src = seg == 0 ? qw : (seg == 1 ? kw : vw);
        wt[idx] = __float2bfloat16(src[k*128 + n]);
    } else {
        int i2 = idx - 49152;                     // 0..147455
        int st = i2 >> 13;                        // slab 0..17
        int rel = i2 & 8191;
        int r = rel >> 6, c = rel & 63;
        float v;
        if (st < 2) {
            v = pw[(st*64 + c)*128 + r];
        } else {
            int t = st - 2, ch = t >> 2, s = t & 3;
            if (s < 2) v = f1w[(s*64 + c)*512 + ch*128 + r];
            else       v = f2w[(ch*128 + (s-2)*64 + c)*128 + r];
        }
        tb[i2] = __float2bfloat16(v);
    }
}

// ---------------- LayerNorm (fused with shift+window gather), bf16 out -----
__global__ void ln_kernel(const float* __restrict__ in, const float* __restrict__ gamma,
                          const float* __restrict__ beta, __nv_bfloat16* __restrict__ out)
{
    int token = blockIdx.x * 8 + (threadIdx.x >> 5);
    int lane  = threadIdx.x & 31;
    int src = perm_m(token);
    float4 xv = ((const float4*)in)[(size_t)src*32 + lane];
    float s  = xv.x + xv.y + xv.z + xv.w;
    float sq = xv.x*xv.x + xv.y*xv.y + xv.z*xv.z + xv.w*xv.w;
    #pragma unroll
    for (int o = 16; o; o >>= 1) {
        s  += __shfl_xor_sync(0xffffffffu, s,  o);
        sq += __shfl_xor_sync(0xffffffffu, sq, o);
    }
    float mean = s * (1.f/128.f);
    float var  = sq * (1.f/128.f) - mean*mean;
    float rstd = rsqrtf(var + 1e-5f);
    float4 g  = ((const float4*)gamma)[lane];
    float4 bt = ((const float4*)beta)[lane];
    uint2 pk;
    pk.x = packbf((xv.x - mean)*rstd*g.x + bt.x, (xv.y - mean)*rstd*g.y + bt.y);
    pk.y = packbf((xv.z - mean)*rstd*g.z + bt.z, (xv.w - mean)*rstd*g.w + bt.w);
    ((uint2*)out)[(size_t)token*32 + lane] = pk;
}

// ---------------- fused QKV + windowed attention (unrolled single-barrier) -
#define AQ_XW   0
#define AQ_WB   4352
#define AQ_PS   0
#define AQ_QS   9472
#define AQ_KS   13824
#define AQ_VT   18176
#define AQ_RPB  22784
#define AQ_LAB  23684
#define AQ_RM   23748
#define AQ_RS   24260
#define AQ_SMEM (24772*4)

__global__ void __launch_bounds__(256, 2) qkv_attn(
    const __nv_bfloat16* __restrict__ xw,
    const __nv_bfloat16* __restrict__ wqkv,   // [384][128]
    const float* __restrict__ qb, const float* __restrict__ kb, const float* __restrict__ vb,
    const float* __restrict__ rpb, float scale,
    __nv_bfloat16* __restrict__ out)
{
    extern __shared__ unsigned sm[];
    unsigned* Qs = sm + AQ_QS;
    unsigned* Ks = sm + AQ_KS;
    float*    rpb_s = (float*)(sm + AQ_RPB);
    int*      lab_s = (int*)(sm + AQ_LAB);
    float*    redm  = (float*)(sm + AQ_RM);
    float*    redsm = (float*)(sm + AQ_RS);
    unsigned short* vtb = (unsigned short*)(sm + AQ_VT);

    const int win  = blockIdx.x;
    const int tid  = threadIdx.x;
    const int lane = tid & 31;
    const int lr   = lane >> 2;
    const int lc   = lane & 3;
    const int wid  = tid >> 5;
    const int wloc = win & 1023;
    const int wh = wloc >> 5, ww = wloc & 31;

    const int a_lm   = (lane & 7) + ((lane >> 3) & 1)*8;
    const int a_kadd = (lane >> 4) << 2;
    const int b_lm   = lane & 7;
    const int b_kadd = ((lane >> 3) & 1) << 2;

    const unsigned sm_u  = (unsigned)__cvta_generic_to_shared(sm);
    const unsigned xw_u  = sm_u + AQ_XW*4;
    const unsigned wb_u  = sm_u + AQ_WB*4;
    const unsigned qs_u  = sm_u + AQ_QS*4;
    const unsigned ks_u  = sm_u + AQ_KS*4;
    const unsigned WBB = 128*20*4;

    const int wm = wid >> 2;
    const int wn = wid & 3;
    const int a_row = wm*32 + lr;

    // per-thread constant frag address pieces for the QKV phase
    const unsigned qa_off0 = ((wm*32 + a_lm)*68      + a_kadd)*4;
    const unsigned qa_off1 = ((wm*32 + 16 + a_lm)*68 + a_kadd)*4;
    const unsigned qb_off  = ((wn*32 + b_lm)*20 + b_kadd)*4;

    #define WISSUE(st_) { \
        const __nv_bfloat16* W_ = wqkv + (size_t)((st_) >> 2)*128*128 + ((st_) & 3)*32; \
        const unsigned dst_ = wb_u + (((st_) & 1))*WBB; \
        _Pragma("unroll") \
        for (int s_ = 0; s_ < 2; s_++) { \
            int slot_ = tid + 256*s_; \
            int rw_ = slot_ >> 2, cc_ = slot_ & 3; \
            cp16(dst_ + (rw_*20 + cc_*4)*4, W_ + (size_t)rw_*128 + cc_*8); \
        } CP_COMMIT; }

    // prologue: Xw tile + weight stage 0 in one group
    {
        const __nv_bfloat16* xp = xw + (size_t)win*64*128;
        #pragma unroll
        for (int s_ = 0; s_ < 4; s_++) {
            int slot = tid + 256*s_;
            int row = slot >> 4, c4 = slot & 15;
            cp16(xw_u + (row*68 + c4*4)*4, xp + (size_t)row*128 + c4*8);
        }
        WISSUE(0);
    }

    for (int idx = tid; idx < 900; idx += 256) rpb_s[idx] = rpb[idx];
    if (tid < 64) lab_s[tid] = 3*region(wh*8 + (tid >> 3)) + region(ww*8 + (tid & 7));

    float acc[2][4][4];

    #define QSTAGE_MMA(KOFF, STC) { \
        const unsigned bslu = wb_u + ((STC) & 1)*WBB; \
        _Pragma("unroll") \
        for (int kk2 = 0; kk2 < 16; kk2 += 8) { \
            unsigned afr[2][4]; \
            ldsm4(afr[0], xw_u + qa_off0 + ((KOFF) + kk2)*4); \
            ldsm4(afr[1], xw_u + qa_off1 + ((KOFF) + kk2)*4); \
            _Pragma("unroll") \
            for (int j = 0; j < 4; j++) { \
                unsigned bfr[2]; \
                ldsm2(bfr, bslu + qb_off + (j*8*20 + kk2)*4); \
                _Pragma("unroll") \
                for (int i = 0; i < 2; i++) \
                    mma_bf16(acc[i][j], afr[i], bfr); \
            } } }

    #define DO_QSTAGE(STC, HASNEXT) { \
        CP_WAIT0; \
        __syncthreads(); \
        if (HASNEXT) WISSUE((STC) + 1); \
        if (((STC) & 3) == 0) { \
            _Pragma("unroll") \
            for (int i = 0; i < 2; i++) \
                _Pragma("unroll") \
                for (int j = 0; j < 4; j++) \
                    _Pragma("unroll") \
                    for (int c = 0; c < 4; c++) acc[i][j][c] = 0.f; \
        } \
        QSTAGE_MMA(((STC) & 3)*16, STC); }

    // ---- Q chunk: stages 0..3 ----
    DO_QSTAGE(0, 1); DO_QSTAGE(1, 1); DO_QSTAGE(2, 1); DO_QSTAGE(3, 1);
    #pragma unroll
    for (int i = 0; i < 2; i++) {
        #pragma unroll
        for (int half = 0; half < 2; half++) {
            int row = a_row + i*16 + half*8;
            #pragma unroll
            for (int j = 0; j < 4; j++) {
                int n = wn*32 + j*8 + 2*lc;
                float v0 = (acc[i][j][half*2 + 0] + qb[n]) * scale;
                float v1 = (acc[i][j][half*2 + 1] + qb[n+1]) * scale;
                Qs[row*68 + wn*16 + j*4 + lc] = packbf(v0, v1);
            }
        }
    }

    // ---- K chunk: stages 4..7 ----
    DO_QSTAGE(4, 1); DO_QSTAGE(5, 1); DO_QSTAGE(6, 1); DO_QSTAGE(7, 1);
    #pragma unroll
    for (int i = 0; i < 2; i++) {
        #pragma unroll
        for (int half = 0; half < 2; half++) {
            int row = a_row + i*16 + half*8;
            #pragma unroll
            for (int j = 0; j < 4; j++) {
                int n = wn*32 + j*8 + 2*lc;
                float v0 = acc[i][j][half*2 + 0] + kb[n];
                float v1 = acc[i][j][half*2 + 1] + kb[n+1];
                Ks[row*68 + wn*16 + j*4 + lc] = packbf(v0, v1);
            }
        }
    }

    // ---- V chunk: stages 8..11 ----
    DO_QSTAGE(8, 1); DO_QSTAGE(9, 1); DO_QSTAGE(10, 1); DO_QSTAGE(11, 0);
    #pragma unroll
    for (int i = 0; i < 2; i++) {
        #pragma unroll
        for (int half = 0; half < 2; half++) {
            int row = a_row + i*16 + half*8;
            #pragma unroll
            for (int j = 0; j < 4; j++) {
                int n = wn*32 + j*8 + 2*lc;
                float v0 = acc[i][j][half*2 + 0] + vb[n];
                float v1 = acc[i][j][half*2 + 1] + vb[n+1];
                int h0 = n >> 5,  nl0 = n & 31;
                int h1 = (n+1) >> 5, nl1 = (n+1) & 31;
                vtb[h0*2304 + nl0*72 + row] = bf16u(v0);
                vtb[h1*2304 + nl1*72 + row] = bf16u(v1);
            }
        }
    }
    #undef DO_QSTAGE
    #undef QSTAGE_MMA
    #undef WISSUE
    __syncthreads();

    // ---- attention phase: warp = (head, key-half) ----
    const int head = wid >> 1;
    const int w    = wid & 1;
    const unsigned ps_u = sm_u + AQ_PS*4 + head*2304*4;   // aliases Xw/Wb
    const unsigned vt_u = sm_u + AQ_VT*4 + head*1152*4;
    unsigned* Ps   = sm + AQ_PS + head*2304;
    float* redm_h  = redm  + head*128;
    float* reds_h  = redsm + head*128;
    const int hq   = head*16;

    float s[4][4][4];
    #pragma unroll
    for (int i = 0; i < 4; i++)
        #pragma unroll
        for (int j = 0; j < 4; j++)
            #pragma unroll
            for (int c = 0; c < 4; c++) s[i][j][c] = 0.f;

    const int nb0 = w*32;
    #pragma unroll
    for (int kk2 = 0; kk2 < 16; kk2 += 8) {
        unsigned afr[4][4], bfr[4][2];
        #pragma unroll
        for (int i = 0; i < 4; i++)
            ldsm4(afr[i], qs_u + ((i*16 + a_lm)*68 + hq + kk2 + a_kadd)*4);
        #pragma unroll
        for (int j = 0; j < 4; j++)
            ldsm2(bfr[j], ks_u + ((nb0 + j*8 + b_lm)*68 + hq + kk2 + b_kadd)*4);
        #pragma unroll
        for (int i = 0; i < 4; i++)
            #pragma unroll
            for (int j = 0; j < 4; j++)
                mma_bf16(s[i][j], afr[i], bfr[j]);
    }

    #pragma unroll
    for (int i = 0; i < 4; i++) {
        #pragma unroll
        for (int half = 0; half < 2; half++) {
            int r = i*16 + lr + half*8;
            int labr = lab_s[r];
            int ti = r >> 3, tj = r & 7;
            float m_ = -1e30f;
            #pragma unroll
            for (int j = 0; j < 4; j++) {
                #pragma unroll
                for (int e = 0; e < 2; e++) {
                    int c = nb0 + j*8 + 2*lc + e;
                    int ki = c >> 3, kj = c & 7;
                    float val = s[i][j][half*2 + e]
                              + rpb_s[((ti - ki + 7)*15 + (tj - kj + 7))*4 + head];
                    if (lab_s[c] != labr) val -= 100.f;
                    s[i][j][half*2 + e] = val;
                    m_ = fmaxf(m_, val);
                }
            }
            m_ = fmaxf(m_, __shfl_xor_sync(0xffffffffu, m_, 1));
            m_ = fmaxf(m_, __shfl_xor_sync(0xffffffffu, m_, 2));
            if (lc == 0) redm_h[r*2 + w] = m_;
        }
    }
    __syncthreads();

    #pragma unroll
    for (int i = 0; i < 4; i++) {
        #pragma unroll
        for (int half = 0; half < 2; half++) {
            int r = i*16 + lr + half*8;
            float mx = fmaxf(redm_h[r*2], redm_h[r*2 + 1]);
            float sum = 0.f;
            #pragma unroll
            for (int j = 0; j < 4; j++) {
                float e0 = __expf(s[i][j][half*2 + 0] - mx);
                float e1 = __expf(s[i][j][half*2 + 1] - mx);
                sum += e0 + e1;
                Ps[r*36 + 16*w + j*4 + lc] = packbf(e0, e1);
            }
            sum += __shfl_xor_sync(0xffffffffu, sum, 1);
            sum += __shfl_xor_sync(0xffffffffu, sum, 2);
            if (lc == 0) reds_h[r*2 + w] = sum;
        }
    }
    __syncthreads();

    float o[2][4][4];
    #pragma unroll
    for (int i = 0; i < 2; i++)
        #pragma unroll
        for (int j = 0; j < 4; j++)
            #pragma unroll
            for (int c = 0; c < 4; c++) o[i][j][c] = 0.f;

    const int mb = w*32;
    #pragma unroll
    for (int kb = 0; kb < 4; kb++) {
        unsigned afr[2][4], bfr[4][2];
        #pragma unroll
        for (int i = 0; i < 2; i++)
            ldsm4(afr[i], ps_u + ((mb + i*16 + a_lm)*36 + kb*8 + a_kadd)*4);
        #pragma unroll
        for (int j = 0; j < 4; j++)
            ldsm2(bfr[j], vt_u + ((j*8 + b_lm)*36 + kb*8 + b_kadd)*4);
        #pragma unroll
        for (int i = 0; i < 2; i++)
            #pragma unroll
            for (int j = 0; j < 4; j++)
                mma_bf16(o[i][j], afr[i], bfr[j]);
    }

    #pragma unroll
    for (int i = 0; i < 2; i++) {
        #pragma unroll
        for (int half = 0; half < 2; half++) {
            int r = mb + i*16 + lr + half*8;
            float inv = 1.f / (reds_h[r*2] + reds_h[r*2 + 1]);
            size_t ob = (size_t)win*64*128 + (size_t)r*128 + head*32;
            #pragma unroll
            for (int j = 0; j < 4; j++) {
                int n = j*8 + 2*lc;
                float v0 = o[i][j][half*2 + 0] * inv;
                float v1 = o[i][j][half*2 + 1] * inv;
                *(unsigned*)&out[ob + n] = packbf(v0, v1);
            }
        }
    }
}

// ---------------- fused tail: R15 (M=64, 2 blocks/SM, unrolled) ------------
#define T_AS 0
#define T_L2 4352
#define T_XS 8704
#define T_BS 17152
#define T_RS 26368
#define T_RQ 26624
#define TAIL_SMEM (26880*4)

__global__ void __launch_bounds__(256, 2) tail_fused(
    const __nv_bfloat16* __restrict__ ao,
    const __nv_bfloat16* __restrict__ blob,
    const float* __restrict__ pb, const float* __restrict__ b1, const float* __restrict__ b2,
    const float* __restrict__ hs,
    const float* __restrict__ gamma, const float* __restrict__ beta,
    float* __restrict__ outp)
{
    extern __shared__ unsigned sm[];
    unsigned* L2s = sm + T_L2;
    float*    Xs  = (float*)(sm + T_XS);
    float*    red_s = (float*)(sm + T_RS);
    float*    red_q = (float*)(sm + T_RQ);
    unsigned* Hc  = sm + T_AS;     // Hc aliases As (dead after proj)

    const int tid  = threadIdx.x;
    const int lane = tid & 31;
    const int lr   = lane >> 2;
    const int lc   = lane & 3;
    const int w    = tid >> 5;
    const int wm   = w >> 2;
    const int wn   = w & 3;
    const int m0   = blockIdx.x * 64;
    const int a_row = wm*32 + lr;

    const int a_lm   = (lane & 7) + ((lane >> 3) & 1)*8;
    const int a_kadd = (lane >> 4) << 2;
    const int b_lm   = lane & 7;
    const int b_kadd = ((lane >> 3) & 1) << 2;

    const unsigned sm_u = (unsigned)__cvta_generic_to_shared(sm);
    const unsigned as_u = sm_u + T_AS*4;
    const unsigned l2_u = sm_u + T_L2*4;
    const unsigned xs_u = sm_u + T_XS*4;
    const unsigned bs_u = sm_u + T_BS*4;
    const unsigned hc_u = as_u;
    const unsigned BSB = 128*36*4;

    const unsigned a_off0 = ((wm*32 + a_lm)*68      + a_kadd)*4;
    const unsigned a_off1 = ((wm*32 + 16 + a_lm)*68 + a_kadd)*4;
    const unsigned b_off  = ((wn*32 + b_lm)*36 + b_kadd)*4;

    #define ISSUE_ST(st_) { \
        const __nv_bfloat16* W_ = blob + (size_t)(st_)*8192; \
        const unsigned dst_ = bs_u + (((st_) & 1))*BSB; \
        _Pragma("unroll") \
        for (int s_ = 0; s_ < 4; s_++) { \
            int slot_ = tid + 256*s_; \
            int rw_ = slot_ >> 3, c_ = slot_ & 7; \
            cp16(dst_ + (rw_*36 + c_*4)*4, W_ + rw_*64 + c_*8); \
        } CP_COMMIT; }

    {
        const __nv_bfloat16* aop = ao + (size_t)m0 * 128;
        #pragma unroll
        for (int s_ = 0; s_ < 4; s_++) {
            int slot = tid + 256*s_;
            int row = slot >> 4, c4 = slot & 15;
            cp16(as_u + (row*68 + c4*4)*4, aop + (size_t)row*128 + c4*8);
        }
        #pragma unroll
        for (int s_ = 0; s_ < 8; s_++) {
            int slot = tid + 256*s_;
            int row = slot >> 5, q4 = slot & 31;
            cp16(xs_u + (row*132 + q4*4)*4,
                 hs + (size_t)perm_m(m0 + row)*128 + q4*4);
        }
        ISSUE_ST(0);
    }

    float acc1[2][4][4], acc2[2][4][4];
    #pragma unroll
    for (int i = 0; i < 2; i++)
        #pragma unroll
        for (int j = 0; j < 4; j++)
            #pragma unroll
            for (int c = 0; c < 4; c++) { acc1[i][j][c] = 0.f; acc2[i][j][c] = 0.f; }

    #define STAGE_MMA(SRCU, KOFF, ACC, STC) { \
        const unsigned bslu = bs_u + ((STC) & 1)*BSB; \
        _Pragma("unroll") \
        for (int kk2 = 0; kk2 < 32; kk2 += 8) { \
            unsigned afr[2][4]; \
            ldsm4(afr[0], (SRCU) + a_off0 + ((KOFF) + kk2)*4); \
            ldsm4(afr[1], (SRCU) + a_off1 + ((KOFF) + kk2)*4); \
            _Pragma("unroll") \
            for (int j = 0; j < 4; j++) { \
                unsigned bfr[2]; \
                ldsm2(bfr, bslu + b_off + (j*8*36 + kk2)*4); \
                _Pragma("unroll") \
                for (int i = 0; i < 2; i++) \
                    mma_bf16(ACC[i][j], afr[i], bfr); \
            } } }

    #define DO_STAGE(STC, HASNEXT, SRCU, KOFF, ACC) { \
        CP_WAIT0; \
        __syncthreads(); \
        if (HASNEXT) ISSUE_ST((STC) + 1); \
        STAGE_MMA(SRCU, KOFF, ACC, STC); }

    DO_STAGE(0, 1, as_u, 0,  acc1);
    DO_STAGE(1, 1, as_u, 32, acc1);

    {
        #pragma unroll
        for (int i = 0; i < 2; i++) {
            #pragma unroll
            for (int half = 0; half < 2; half++) {
                int row = a_row + i*16 + half*8;
                float s = 0.f, q = 0.f;
                #pragma unroll
                for (int j = 0; j < 4; j++) {
                    int n = wn*32 + j*8 + 2*lc;
                    float x0 = acc1[i][j][half*2 + 0] + pb[n]   + Xs[row*132 + n];
                    float x1 = acc1[i][j][half*2 + 1] + pb[n+1] + Xs[row*132 + n + 1];
                    *(float2*)&Xs[row*132 + n] = make_float2(x0, x1);
                    s += x0 + x1;
                    q += x0*x0 + x1*x1;
                }
                s += __shfl_xor_sync(0xffffffffu, s, 1);
                s += __shfl_xor_sync(0xffffffffu, s, 2);
                q += __shfl_xor_sync(0xffffffffu, q, 1);
                q += __shfl_xor_sync(0xffffffffu, q, 2);
                if (lc == 0) { red_s[row*4 + wn] = s; red_q[row*4 + wn] = q; }
            }
        }
        __syncthreads();
        #pragma unroll
        for (int i = 0; i < 2; i++) {
            #pragma unroll
            for (int half = 0; half < 2; half++) {
                int row = a_row + i*16 + half*8;
                float s = red_s[row*4+0] + red_s[row*4+1] + red_s[row*4+2] + red_s[row*4+3];
                float q = red_q[row*4+0] + red_q[row*4+1] + red_q[row*4+2] + red_q[row*4+3];
                float mu = s * (1.f/128.f);
                float var = q * (1.f/128.f) - mu*mu;
                float rstd = rsqrtf(var + 1e-5f);
                #pragma unroll
                for (int j = 0; j < 4; j++) {
                    int n = wn*32 + j*8 + 2*lc;
                    float x0 = Xs[row*132 + n];
                    float x1 = Xs[row*132 + n + 1];
                    float l0 = (x0 - mu)*rstd*gamma[n]   + beta[n];
                    float l1 = (x1 - mu)*rstd*gamma[n+1] + beta[n+1];
                    L2s[row*68 + wn*16 + j*4 + lc] = packbf(l0, l1);
                }
            }
        }
    }

    #pragma unroll
    for (int ch = 0; ch < 4; ch++) {
        const int st0 = 2 + ch*4;
        #pragma unroll
        for (int i = 0; i < 2; i++)
            #pragma unroll
            for (int j = 0; j < 4; j++)
                #pragma unroll
                for (int c = 0; c < 4; c++) acc1[i][j][c] = 0.f;

        DO_STAGE(st0 + 0, 1, l2_u, 0,  acc1);
        DO_STAGE(st0 + 1, 1, l2_u, 32, acc1);

        #pragma unroll
        for (int i = 0; i < 2; i++) {
            #pragma unroll
            for (int half = 0; half < 2; half++) {
                int row = a_row + i*16 + half*8;
                #pragma unroll
                for (int j = 0; j < 4; j++) {
                    int n = wn*32 + j*8 + 2*lc;
                    float v0 = gelu_f(acc1[i][j][half*2 + 0] + b1[ch*128 + n]);
                    float v1 = gelu_f(acc1[i][j][half*2 + 1] + b1[ch*128 + n + 1]);
                    Hc[row*68 + wn*16 + j*4 + lc] = packbf(v0, v1);
                }
            }
        }

        DO_STAGE(st0 + 2, 1,               hc_u, 0,  acc2);
        DO_STAGE(st0 + 3, (st0 + 3) < 17,  hc_u, 32, acc2);
    }
    #undef DO_STAGE
    #undef STAGE_MMA
    #undef ISSUE_ST

    #pragma unroll
    for (int i = 0; i < 2; i++) {
        #pragma unroll
        for (int half = 0; half < 2; half++) {
            int rloc = a_row + i*16 + half*8;
            int m = m0 + rloc;
            size_t dstrow = (size_t)perm_m(m) * 128;
            #pragma unroll
            for (int j = 0; j < 4; j++) {
                int n = wn*32 + j*8 + 2*lc;
                float v0 = acc2[i][j][half*2 + 0] + b2[n]   + Xs[rloc*132 + n];
                float v1 = acc2[i][j][half*2 + 1] + b2[n+1] + Xs[rloc*132 + n + 1];
                *(float2*)&outp[dstrow + n] = make_float2(v0, v1);
            }
        }
    }
}

// ---------------------------------------------------------------------------
extern "C" void kernel_launch(void* const* d_in, const int* in_sizes, int n_in,
                              void* d_out, int out_size)
{
    const float* hs   = (const float*)d_in[0];
    const float* l1s  = (const float*)d_in[1];
    const float* l1b  = (const float*)d_in[2];
    const float* qw   = (const float*)d_in[3];
    const float* qb   = (const float*)d_in[4];
    const float* kw   = (const float*)d_in[5];
    const float* kb   = (const float*)d_in[6];
    const float* vw   = (const float*)d_in[7];
    const float* vb   = (const float*)d_in[8];
    const float* pw   = (const float*)d_in[9];
    const float* pb   = (const float*)d_in[10];
    const float* rpb  = (const float*)d_in[11];
    const float* l2s  = (const float*)d_in[12];
    const float* l2b  = (const float*)d_in[13];
    const float* f1w  = (const float*)d_in[14];
    const float* f1b  = (const float*)d_in[15];
    const float* f2w  = (const float*)d_in[16];
    const float* f2b  = (const float*)d_in[17];
    float* outp = (float*)d_out;

    __nv_bfloat16 *xw, *ao, *wt, *tb;
    cudaGetSymbolAddress((void**)&xw, g_xw);
    cudaGetSymbolAddress((void**)&ao, g_ao);
    cudaGetSymbolAddress((void**)&wt, g_wt);
    cudaGetSymbolAddress((void**)&tb, g_tb);

    cudaFuncSetAttribute(qkv_attn,   cudaFuncAttributeMaxDynamicSharedMemorySize, AQ_SMEM);
    cudaFuncSetAttribute(tail_fused, cudaFuncAttributeMaxDynamicSharedMemorySize, TAIL_SMEM);

    const float qscale = 0.17677669529663687f;  // 1/sqrt(32)

    // 0. fused weight prep (Wqkv + tail blob)
    prep_all<<<768, 256>>>(qw, kw, vw, pw, f1w, f2w, wt, tb);
    // 1. LN1 + shift + window partition (bf16 out)
    ln_kernel<<<MTOK/8, 256>>>(hs, l1s, l1b, xw);
    // 2. fused QKV + windowed attention (unrolled single-barrier)
    qkv_attn<<<4096, 256, AQ_SMEM>>>(xw, wt, qb, kb, vb, rpb, qscale, ao);
    // 3. fused tail: R15 config (M=64, 2 blocks/SM)
    tail_fused<<<MTOK/64, 256, TAIL_SMEM>>>(ao, tb, pb, f1b, f2b,
                                            hs, l2s, l2b, outp);
}